// round 2
// baseline (speedup 1.0000x reference)
#include <cuda_runtime.h>

#define NMAX 50000
#define NGRAPH 64
#define ET_MAX 860000

// ---------------- scratch (device globals; no allocations allowed) ----------
__device__ float g_A[NMAX * 256];       // GEMM output (pre-aggregation features)
__device__ float g_Bb[NMAX * 256];      // aggregation output (next layer input)
__device__ float g_als[NMAX * 4];
__device__ float g_ald[NMAX * 4];
__device__ int   g_deg[NMAX];
__device__ int   g_off[NMAX + 1];
__device__ int   g_cur[NMAX];
__device__ int   g_csrc[ET_MAX];
__device__ float g_pool[NGRAPH * 64];
__device__ float g_cnt[NGRAPH];

// ---------------- CSR build --------------------------------------------------
__global__ void zero_int_kernel(int* p, int n) {
    int i = blockIdx.x * blockDim.x + threadIdx.x;
    if (i < n) p[i] = 0;
}

__global__ void hist_kernel(const int* __restrict__ ei, int E, int ET,
                            int* __restrict__ deg) {
    int e = blockIdx.x * blockDim.x + threadIdx.x;
    if (e >= ET) return;
    int d = (e < E) ? ei[E + e] : (e - E);
    atomicAdd(&deg[d], 1);
}

// single-block inclusive scan over deg -> off[1..n], off[0]=0, cur[i]=off[i]
__global__ void scan_kernel(const int* __restrict__ deg, int* __restrict__ off,
                            int* __restrict__ cur, int n) {
    __shared__ int sh[1024];
    __shared__ int carry;
    if (threadIdx.x == 0) { carry = 0; off[0] = 0; }
    __syncthreads();
    for (int base = 0; base < n; base += 1024) {
        int i = base + threadIdx.x;
        int v = (i < n) ? deg[i] : 0;
        sh[threadIdx.x] = v;
        __syncthreads();
        for (int d = 1; d < 1024; d <<= 1) {
            int t = (threadIdx.x >= d) ? sh[threadIdx.x - d] : 0;
            __syncthreads();
            sh[threadIdx.x] += t;
            __syncthreads();
        }
        if (i < n) {
            int incl = carry + sh[threadIdx.x];
            off[i + 1] = incl;
            cur[i] = incl - v;
        }
        __syncthreads();
        if (threadIdx.x == 0) carry += sh[1023];
        __syncthreads();
    }
}

__global__ void scatter_kernel(const int* __restrict__ ei, int E, int ET,
                               int* __restrict__ cur, int* __restrict__ csrc) {
    int e = blockIdx.x * blockDim.x + threadIdx.x;
    if (e >= ET) return;
    int s, d;
    if (e < E) { s = ei[e]; d = ei[E + e]; }
    else       { s = e - E; d = e - E; }
    int pos = atomicAdd(&cur[d], 1);
    csrc[pos] = s;
}

// ---------------- GEMM: C[M,Nc] = A[M,K] @ W[K,Nc], fp32 -------------------
__global__ void gemm_kernel(const float* __restrict__ A, const float* __restrict__ W,
                            float* __restrict__ C, int M, int K, int Nc) {
    __shared__ __align__(16) float As[64][17];
    __shared__ __align__(16) float Bs[16][64];
    int tid = threadIdx.x;                 // 256 threads
    int rowBase = blockIdx.x * 64;
    int colBase = blockIdx.y * 64;
    int ty = tid >> 4, tx = tid & 15;
    int arow = tid >> 2;                   // 0..63
    int acol4 = (tid & 3) * 4;             // 0,4,8,12
    int brow = tid >> 4;                   // 0..15
    int bcol4 = (tid & 15) * 4;            // 0..60

    float acc[4][4];
#pragma unroll
    for (int i = 0; i < 4; i++)
#pragma unroll
        for (int j = 0; j < 4; j++) acc[i][j] = 0.f;

    for (int k0 = 0; k0 < K; k0 += 16) {
        int gr = rowBase + arow;
        float4 av = make_float4(0.f, 0.f, 0.f, 0.f);
        if (gr < M)
            av = *reinterpret_cast<const float4*>(A + (size_t)gr * K + k0 + acol4);
        As[arow][acol4 + 0] = av.x;
        As[arow][acol4 + 1] = av.y;
        As[arow][acol4 + 2] = av.z;
        As[arow][acol4 + 3] = av.w;
        float4 bv = *reinterpret_cast<const float4*>(
            W + (size_t)(k0 + brow) * Nc + colBase + bcol4);
        *reinterpret_cast<float4*>(&Bs[brow][bcol4]) = bv;
        __syncthreads();
#pragma unroll
        for (int kk = 0; kk < 16; kk++) {
            float a0 = As[ty * 4 + 0][kk];
            float a1 = As[ty * 4 + 1][kk];
            float a2 = As[ty * 4 + 2][kk];
            float a3 = As[ty * 4 + 3][kk];
            float4 b4 = *reinterpret_cast<const float4*>(&Bs[kk][tx * 4]);
            acc[0][0] += a0 * b4.x; acc[0][1] += a0 * b4.y; acc[0][2] += a0 * b4.z; acc[0][3] += a0 * b4.w;
            acc[1][0] += a1 * b4.x; acc[1][1] += a1 * b4.y; acc[1][2] += a1 * b4.z; acc[1][3] += a1 * b4.w;
            acc[2][0] += a2 * b4.x; acc[2][1] += a2 * b4.y; acc[2][2] += a2 * b4.z; acc[2][3] += a2 * b4.w;
            acc[3][0] += a3 * b4.x; acc[3][1] += a3 * b4.y; acc[3][2] += a3 * b4.z; acc[3][3] += a3 * b4.w;
        }
        __syncthreads();
    }
#pragma unroll
    for (int i = 0; i < 4; i++) {
        int gr = rowBase + ty * 4 + i;
        if (gr < M) {
            float* cp = C + (size_t)gr * Nc + colBase + tx * 4;
            cp[0] = acc[i][0]; cp[1] = acc[i][1]; cp[2] = acc[i][2]; cp[3] = acc[i][3];
        }
    }
}

// ---------------- attention coefficients: al_s/al_d per (node, head) -------
template <int H, int C>
__global__ void attn_kernel(const float* __restrict__ h, const float* __restrict__ a_src,
                            const float* __restrict__ a_dst,
                            float* __restrict__ als, float* __restrict__ ald, int n) {
    int node = blockIdx.x;
    int w = threadIdx.x >> 5, lane = threadIdx.x & 31;
    if (node >= n) return;
    float ss = 0.f, dd = 0.f;
    const float* hp = h + (size_t)node * H * C + w * C;
#pragma unroll
    for (int c0 = 0; c0 < C; c0 += 32) {
        int c = c0 + lane;
        float hv = hp[c];
        ss += hv * a_src[w * C + c];
        dd += hv * a_dst[w * C + c];
    }
#pragma unroll
    for (int o = 16; o > 0; o >>= 1) {
        ss += __shfl_xor_sync(~0u, ss, o);
        dd += __shfl_xor_sync(~0u, dd, o);
    }
    if (lane == 0) { als[node * H + w] = ss; ald[node * H + w] = dd; }
}

// ---------------- fused per-node softmax + aggregation (warp per node) -----
template <int H, int C, bool RELU>
__global__ void agg_kernel(const float* __restrict__ h, const float* __restrict__ als,
                           const float* __restrict__ ald, const float* __restrict__ bias,
                           const int* __restrict__ off, const int* __restrict__ csrc,
                           float* __restrict__ out, int n) {
    int node = blockIdx.x * 4 + (threadIdx.x >> 5);
    int lane = threadIdx.x & 31;
    if (node >= n) return;
    int beg = off[node], end = off[node + 1];

    float aldv[H], mx[H], sm[H];
#pragma unroll
    for (int t = 0; t < H; t++) {
        aldv[t] = ald[node * H + t];
        mx[t] = -1e30f;
        sm[t] = 0.f;
    }
    for (int i = beg + lane; i < end; i += 32) {
        int s = csrc[i];
#pragma unroll
        for (int t = 0; t < H; t++) {
            float l = als[s * H + t] + aldv[t];
            l = l > 0.f ? l : 0.2f * l;
            mx[t] = fmaxf(mx[t], l);
        }
    }
#pragma unroll
    for (int t = 0; t < H; t++)
#pragma unroll
        for (int o = 16; o > 0; o >>= 1) mx[t] = fmaxf(mx[t], __shfl_xor_sync(~0u, mx[t], o));

    for (int i = beg + lane; i < end; i += 32) {
        int s = csrc[i];
#pragma unroll
        for (int t = 0; t < H; t++) {
            float l = als[s * H + t] + aldv[t];
            l = l > 0.f ? l : 0.2f * l;
            sm[t] += __expf(l - mx[t]);
        }
    }
#pragma unroll
    for (int t = 0; t < H; t++)
#pragma unroll
        for (int o = 16; o > 0; o >>= 1) sm[t] += __shfl_xor_sync(~0u, sm[t], o);

    constexpr int LPH = 32 / H;       // lanes per head
    constexpr int CPL = (H * C) / 32; // channels per lane
    int head = lane / LPH;
    int cb = (lane % LPH) * CPL;

    float mxh = mx[0], aldh = aldv[0], invh = 1.f / (sm[0] + 1e-16f);
#pragma unroll
    for (int t = 1; t < H; t++)
        if (head == t) { mxh = mx[t]; aldh = aldv[t]; invh = 1.f / (sm[t] + 1e-16f); }

    float acc[CPL];
#pragma unroll
    for (int j = 0; j < CPL; j++) acc[j] = 0.f;

    for (int i = beg; i < end; i++) {
        int s = csrc[i];
        float l = als[s * H + head] + aldh;
        l = l > 0.f ? l : 0.2f * l;
        float alpha = __expf(l - mxh) * invh;
        const float* hr = h + (size_t)s * (H * C) + head * C + cb;
        if constexpr (CPL == 8) {
            float4 v0 = *reinterpret_cast<const float4*>(hr);
            float4 v1 = *reinterpret_cast<const float4*>(hr + 4);
            acc[0] += alpha * v0.x; acc[1] += alpha * v0.y;
            acc[2] += alpha * v0.z; acc[3] += alpha * v0.w;
            acc[4] += alpha * v1.x; acc[5] += alpha * v1.y;
            acc[6] += alpha * v1.z; acc[7] += alpha * v1.w;
        } else {
            float2 v = *reinterpret_cast<const float2*>(hr);
            acc[0] += alpha * v.x; acc[1] += alpha * v.y;
        }
    }

    float* op = out + (size_t)node * (H * C) + head * C + cb;
#pragma unroll
    for (int j = 0; j < CPL; j++) {
        float v = acc[j] + bias[head * C + cb + j];
        if (RELU) v = fmaxf(v, 0.f);
        op[j] = v;
    }
}

// ---------------- pooling + final linear ------------------------------------
__global__ void pool_zero_kernel(float* pool, float* cnt) {
    int i = blockIdx.x * blockDim.x + threadIdx.x;
    if (i < NGRAPH * 64) pool[i] = 0.f;
    if (i < NGRAPH) cnt[i] = 0.f;
}

__global__ void pool_add_kernel(const float* __restrict__ g, const int* __restrict__ batch,
                                float* __restrict__ pool, float* __restrict__ cnt, int n) {
    int node = blockIdx.x * 4 + (threadIdx.x >> 5);
    int lane = threadIdx.x & 31;
    if (node >= n) return;
    int b = batch[node];
    atomicAdd(&pool[b * 64 + lane], g[(size_t)node * 64 + lane]);
    atomicAdd(&pool[b * 64 + lane + 32], g[(size_t)node * 64 + lane + 32]);
    if (lane == 0) atomicAdd(&cnt[b], 1.f);
}

__global__ void final_kernel(const float* __restrict__ pool, const float* __restrict__ cnt,
                             const float* __restrict__ linW, const float* __restrict__ linb,
                             float* __restrict__ out) {
    int gph = blockIdx.x;
    int o = threadIdx.x;
    float invc = 1.f / fmaxf(cnt[gph], 1.f);
    float acc = linb[o];
#pragma unroll 8
    for (int c = 0; c < 64; c++) acc += pool[gph * 64 + c] * invc * linW[c * 64 + o];
    out[gph * 64 + o] = acc;
}

// ---------------- driver -----------------------------------------------------
extern "C" void kernel_launch(void* const* d_in, const int* in_sizes, int n_in,
                              void* d_out, int out_size) {
    const float* x     = (const float*)d_in[0];
    const int*   ei    = (const int*)d_in[1];     // int32 (JAX x64 disabled)
    const int*   batch = (const int*)d_in[3];     // int32
    const float* W1   = (const float*)d_in[4];
    const float* a1s  = (const float*)d_in[5];
    const float* a1d  = (const float*)d_in[6];
    const float* b1   = (const float*)d_in[7];
    const float* W2   = (const float*)d_in[8];
    const float* a2s  = (const float*)d_in[9];
    const float* a2d  = (const float*)d_in[10];
    const float* b2   = (const float*)d_in[11];
    const float* W3   = (const float*)d_in[12];
    const float* a3s  = (const float*)d_in[13];
    const float* a3d  = (const float*)d_in[14];
    const float* b3   = (const float*)d_in[15];
    const float* linW = (const float*)d_in[16];
    const float* linb = (const float*)d_in[17];
    float* out = (float*)d_out;

    int n  = in_sizes[0] / 128;
    int E  = in_sizes[1] / 2;
    int ET = E + n;

    float *A, *B, *als, *ald, *pool, *cnt;
    int *deg, *off, *cur, *csrc;
    cudaGetSymbolAddress((void**)&A,    g_A);
    cudaGetSymbolAddress((void**)&B,    g_Bb);
    cudaGetSymbolAddress((void**)&als,  g_als);
    cudaGetSymbolAddress((void**)&ald,  g_ald);
    cudaGetSymbolAddress((void**)&deg,  g_deg);
    cudaGetSymbolAddress((void**)&off,  g_off);
    cudaGetSymbolAddress((void**)&cur,  g_cur);
    cudaGetSymbolAddress((void**)&csrc, g_csrc);
    cudaGetSymbolAddress((void**)&pool, g_pool);
    cudaGetSymbolAddress((void**)&cnt,  g_cnt);

    // ---- CSR by dst (fixed graph; rebuilt every call for determinism rules)
    zero_int_kernel<<<(n + 255) / 256, 256>>>(deg, n);
    hist_kernel<<<(ET + 255) / 256, 256>>>(ei, E, ET, deg);
    scan_kernel<<<1, 1024>>>(deg, off, cur, n);
    scatter_kernel<<<(ET + 255) / 256, 256>>>(ei, E, ET, cur, csrc);

    int nwb = (n + 3) / 4;  // warp-per-node blocks (128 threads)

    // ---- Layer 1: [N,128] @ [128,256], H=4, C=64, ReLU
    {
        dim3 grid((n + 63) / 64, 256 / 64);
        gemm_kernel<<<grid, 256>>>(x, W1, A, n, 128, 256);
        attn_kernel<4, 64><<<n, 128>>>(A, a1s, a1d, als, ald, n);
        agg_kernel<4, 64, true><<<nwb, 128>>>(A, als, ald, b1, off, csrc, B, n);
    }
    // ---- Layer 2: [N,256] @ [256,256], H=4, C=64, ReLU
    {
        dim3 grid((n + 63) / 64, 256 / 64);
        gemm_kernel<<<grid, 256>>>(B, W2, A, n, 256, 256);
        attn_kernel<4, 64><<<n, 128>>>(A, a2s, a2d, als, ald, n);
        agg_kernel<4, 64, true><<<nwb, 128>>>(A, als, ald, b2, off, csrc, B, n);
    }
    // ---- Layer 3: [N,256] @ [256,64], H=1, C=64, no ReLU
    {
        dim3 grid((n + 63) / 64, 64 / 64);
        gemm_kernel<<<grid, 256>>>(B, W3, A, n, 256, 64);
        attn_kernel<1, 64><<<n, 32>>>(A, a3s, a3d, als, ald, n);
        agg_kernel<1, 64, false><<<nwb, 128>>>(A, als, ald, b3, off, csrc, B, n);
    }

    // ---- global mean pool + linear
    pool_zero_kernel<<<16, 256>>>(pool, cnt);
    pool_add_kernel<<<nwb, 128>>>(B, batch, pool, cnt, n);
    final_kernel<<<NGRAPH, 64>>>(pool, cnt, linW, linb, out);
}

// round 3
// speedup vs baseline: 1.3260x; 1.3260x over previous
#include <cuda_runtime.h>
#include <cstdint>

#define NMAX 50000
#define NGRAPH 64
#define ET_MAX 860000

// ---------------- scratch (device globals; no allocations allowed) ----------
__device__ float g_A[NMAX * 256];       // GEMM output (pre-aggregation features)
__device__ float g_Bb[NMAX * 256];      // aggregation output (next layer input)
__device__ float g_als[NMAX * 4];
__device__ float g_ald[NMAX * 4];
__device__ int   g_deg[NMAX];
__device__ int   g_off[NMAX + 1];
__device__ int   g_cur[NMAX];
__device__ int   g_csrc[ET_MAX];
__device__ float g_pool[NGRAPH * 64];
__device__ float g_cnt[NGRAPH];

// ---------------- CSR build --------------------------------------------------
__global__ void zero_int_kernel(int* p, int n) {
    int i = blockIdx.x * blockDim.x + threadIdx.x;
    if (i < n) p[i] = 0;
}

__global__ void hist_kernel(const int* __restrict__ ei, int E, int ET,
                            int* __restrict__ deg) {
    int e = blockIdx.x * blockDim.x + threadIdx.x;
    if (e >= ET) return;
    int d = (e < E) ? ei[E + e] : (e - E);
    atomicAdd(&deg[d], 1);
}

// single-block chunked scan: thread t owns elements [t*chunk, (t+1)*chunk)
__global__ void scan_kernel(const int* __restrict__ deg, int* __restrict__ off,
                            int* __restrict__ cur, int n) {
    __shared__ int warpsum[32];
    const int T = 1024;
    int chunk = (n + T - 1) / T;
    int start = threadIdx.x * chunk;
    int end = start + chunk; if (end > n) end = n;
    int s = 0;
    for (int i = start; i < end; i++) s += deg[i];
    int lane = threadIdx.x & 31, wid = threadIdx.x >> 5;
    int v = s;
#pragma unroll
    for (int o = 1; o < 32; o <<= 1) {
        int t = __shfl_up_sync(~0u, v, o);
        if (lane >= o) v += t;
    }
    if (lane == 31) warpsum[wid] = v;
    __syncthreads();
    if (wid == 0) {
        int w = warpsum[lane];
#pragma unroll
        for (int o = 1; o < 32; o <<= 1) {
            int t = __shfl_up_sync(~0u, w, o);
            if (lane >= o) w += t;
        }
        warpsum[lane] = w;
    }
    __syncthreads();
    int excl = v - s + (wid > 0 ? warpsum[wid - 1] : 0);
    if (threadIdx.x == 0) off[0] = 0;
    int run = excl;
    for (int i = start; i < end; i++) {
        int d = deg[i];
        cur[i] = run;
        run += d;
        off[i + 1] = run;
    }
}

__global__ void scatter_kernel(const int* __restrict__ ei, int E, int ET,
                               int* __restrict__ cur, int* __restrict__ csrc) {
    int e = blockIdx.x * blockDim.x + threadIdx.x;
    if (e >= ET) return;
    int s, d;
    if (e < E) { s = ei[e]; d = ei[E + e]; }
    else       { s = e - E; d = e - E; }
    int pos = atomicAdd(&cur[d], 1);
    csrc[pos] = s;
}

// ---------------- tf32 tensor-core GEMM: C[M,Nc] = A[M,K] @ W[K,Nc] --------
// Block: 128 rows x 64 cols, 256 threads = 8 warps (4 row-warps x 2 col-warps),
// warp tile 32x32 built from m16n8k8 tf32 MMA.
__device__ __forceinline__ uint32_t f2tf32(float v) {
    uint32_t t;
    asm("cvt.rna.tf32.f32 %0, %1;" : "=r"(t) : "f"(v));
    return t;
}

#define APAD 36
#define BPAD 68

__global__ __launch_bounds__(256, 2)
void gemm_tf32_kernel(const float* __restrict__ A, const float* __restrict__ W,
                      float* __restrict__ C, int M, int K, int Nc) {
    __shared__ uint32_t As[128 * APAD];   // [row][k], pad 36 -> bank = lane
    __shared__ uint32_t Bs[32 * BPAD];    // [k][col], pad 68 -> bank = lane

    const int tid = threadIdx.x;
    const int lane = tid & 31;
    const int wid = tid >> 5;
    const int wr = wid >> 1;          // 0..3 warp row
    const int wc = wid & 1;           // 0..1 warp col
    const int gid = lane >> 2;        // groupID 0..7
    const int tig = lane & 3;         // thread-in-group 0..3

    const int rowBase = blockIdx.x * 128;
    const int colBase = blockIdx.y * 64;

    float acc[2][4][4];
#pragma unroll
    for (int mt = 0; mt < 2; mt++)
#pragma unroll
        for (int nt = 0; nt < 4; nt++)
#pragma unroll
            for (int j = 0; j < 4; j++) acc[mt][nt][j] = 0.f;

    for (int k0 = 0; k0 < K; k0 += 32) {
        // load A tile 128x32 (1024 float4, 4 per thread)
#pragma unroll
        for (int i = 0; i < 4; i++) {
            int f4 = tid + i * 256;
            int r = f4 >> 3;                 // 0..127
            int c4 = (f4 & 7) << 2;          // 0,4,...,28
            int gr = rowBase + r;
            float4 v = make_float4(0.f, 0.f, 0.f, 0.f);
            if (gr < M)
                v = *reinterpret_cast<const float4*>(A + (size_t)gr * K + k0 + c4);
            uint32_t* dst = &As[r * APAD + c4];
            dst[0] = f2tf32(v.x); dst[1] = f2tf32(v.y);
            dst[2] = f2tf32(v.z); dst[3] = f2tf32(v.w);
        }
        // load B tile 32x64 (512 float4, 2 per thread)
#pragma unroll
        for (int i = 0; i < 2; i++) {
            int f4 = tid + i * 256;
            int r = f4 >> 4;                 // 0..31 (k)
            int c4 = (f4 & 15) << 2;         // 0..60 (n)
            float4 v = *reinterpret_cast<const float4*>(
                W + (size_t)(k0 + r) * Nc + colBase + c4);
            uint32_t* dst = &Bs[r * BPAD + c4];
            dst[0] = f2tf32(v.x); dst[1] = f2tf32(v.y);
            dst[2] = f2tf32(v.z); dst[3] = f2tf32(v.w);
        }
        __syncthreads();

#pragma unroll
        for (int ks = 0; ks < 4; ks++) {
            const int kk = ks * 8;
            // A fragments for both m16 tiles
            uint32_t af[2][4];
#pragma unroll
            for (int mt = 0; mt < 2; mt++) {
                int r = wr * 32 + mt * 16 + gid;
                af[mt][0] = As[r * APAD + kk + tig];
                af[mt][1] = As[(r + 8) * APAD + kk + tig];
                af[mt][2] = As[r * APAD + kk + tig + 4];
                af[mt][3] = As[(r + 8) * APAD + kk + tig + 4];
            }
            // B fragments for 4 n8 tiles
            uint32_t bf[4][2];
#pragma unroll
            for (int nt = 0; nt < 4; nt++) {
                int c = wc * 32 + nt * 8 + gid;
                bf[nt][0] = Bs[(kk + tig) * BPAD + c];
                bf[nt][1] = Bs[(kk + tig + 4) * BPAD + c];
            }
#pragma unroll
            for (int mt = 0; mt < 2; mt++)
#pragma unroll
                for (int nt = 0; nt < 4; nt++) {
                    asm volatile(
                        "mma.sync.aligned.m16n8k8.row.col.f32.tf32.tf32.f32 "
                        "{%0,%1,%2,%3}, {%4,%5,%6,%7}, {%8,%9}, {%0,%1,%2,%3};"
                        : "+f"(acc[mt][nt][0]), "+f"(acc[mt][nt][1]),
                          "+f"(acc[mt][nt][2]), "+f"(acc[mt][nt][3])
                        : "r"(af[mt][0]), "r"(af[mt][1]),
                          "r"(af[mt][2]), "r"(af[mt][3]),
                          "r"(bf[nt][0]), "r"(bf[nt][1]));
                }
        }
        __syncthreads();
    }

    // epilogue: c0/c1 at (row gid, col tig*2), c2/c3 at row gid+8
#pragma unroll
    for (int mt = 0; mt < 2; mt++) {
        int r0 = rowBase + wr * 32 + mt * 16 + gid;
        int r1 = r0 + 8;
#pragma unroll
        for (int nt = 0; nt < 4; nt++) {
            int c = colBase + wc * 32 + nt * 8 + tig * 2;
            if (r0 < M)
                *reinterpret_cast<float2*>(C + (size_t)r0 * Nc + c) =
                    make_float2(acc[mt][nt][0], acc[mt][nt][1]);
            if (r1 < M)
                *reinterpret_cast<float2*>(C + (size_t)r1 * Nc + c) =
                    make_float2(acc[mt][nt][2], acc[mt][nt][3]);
        }
    }
}

// ---------------- attention coefficients: al_s/al_d per (node, head) -------
template <int H, int C>
__global__ void attn_kernel(const float* __restrict__ h, const float* __restrict__ a_src,
                            const float* __restrict__ a_dst,
                            float* __restrict__ als, float* __restrict__ ald, int n) {
    int node = blockIdx.x;
    int w = threadIdx.x >> 5, lane = threadIdx.x & 31;
    if (node >= n) return;
    float ss = 0.f, dd = 0.f;
    const float* hp = h + (size_t)node * H * C + w * C;
#pragma unroll
    for (int c0 = 0; c0 < C; c0 += 32) {
        int c = c0 + lane;
        float hv = hp[c];
        ss += hv * a_src[w * C + c];
        dd += hv * a_dst[w * C + c];
    }
#pragma unroll
    for (int o = 16; o > 0; o >>= 1) {
        ss += __shfl_xor_sync(~0u, ss, o);
        dd += __shfl_xor_sync(~0u, dd, o);
    }
    if (lane == 0) { als[node * H + w] = ss; ald[node * H + w] = dd; }
}

// ---------------- fused per-node softmax + aggregation (warp per node) -----
template <int H, int C, bool RELU>
__global__ void agg_kernel(const float* __restrict__ h, const float* __restrict__ als,
                           const float* __restrict__ ald, const float* __restrict__ bias,
                           const int* __restrict__ off, const int* __restrict__ csrc,
                           float* __restrict__ out, int n) {
    int node = blockIdx.x * 4 + (threadIdx.x >> 5);
    int lane = threadIdx.x & 31;
    if (node >= n) return;
    int beg = off[node], end = off[node + 1];

    float aldv[H], mx[H], sm[H];
#pragma unroll
    for (int t = 0; t < H; t++) {
        aldv[t] = ald[node * H + t];
        mx[t] = -1e30f;
        sm[t] = 0.f;
    }
    for (int i = beg + lane; i < end; i += 32) {
        int s = csrc[i];
#pragma unroll
        for (int t = 0; t < H; t++) {
            float l = als[s * H + t] + aldv[t];
            l = l > 0.f ? l : 0.2f * l;
            mx[t] = fmaxf(mx[t], l);
        }
    }
#pragma unroll
    for (int t = 0; t < H; t++)
#pragma unroll
        for (int o = 16; o > 0; o >>= 1) mx[t] = fmaxf(mx[t], __shfl_xor_sync(~0u, mx[t], o));

    for (int i = beg + lane; i < end; i += 32) {
        int s = csrc[i];
#pragma unroll
        for (int t = 0; t < H; t++) {
            float l = als[s * H + t] + aldv[t];
            l = l > 0.f ? l : 0.2f * l;
            sm[t] += __expf(l - mx[t]);
        }
    }
#pragma unroll
    for (int t = 0; t < H; t++)
#pragma unroll
        for (int o = 16; o > 0; o >>= 1) sm[t] += __shfl_xor_sync(~0u, sm[t], o);

    constexpr int LPH = 32 / H;       // lanes per head
    constexpr int CPL = (H * C) / 32; // channels per lane
    int head = lane / LPH;
    int cb = (lane % LPH) * CPL;

    float mxh = mx[0], aldh = aldv[0], invh = 1.f / (sm[0] + 1e-16f);
#pragma unroll
    for (int t = 1; t < H; t++)
        if (head == t) { mxh = mx[t]; aldh = aldv[t]; invh = 1.f / (sm[t] + 1e-16f); }

    float acc[CPL];
#pragma unroll
    for (int j = 0; j < CPL; j++) acc[j] = 0.f;

    for (int i = beg; i < end; i++) {
        int s = csrc[i];
        float l = als[s * H + head] + aldh;
        l = l > 0.f ? l : 0.2f * l;
        float alpha = __expf(l - mxh) * invh;
        const float* hr = h + (size_t)s * (H * C) + head * C + cb;
        if constexpr (CPL == 8) {
            float4 v0 = *reinterpret_cast<const float4*>(hr);
            float4 v1 = *reinterpret_cast<const float4*>(hr + 4);
            acc[0] += alpha * v0.x; acc[1] += alpha * v0.y;
            acc[2] += alpha * v0.z; acc[3] += alpha * v0.w;
            acc[4] += alpha * v1.x; acc[5] += alpha * v1.y;
            acc[6] += alpha * v1.z; acc[7] += alpha * v1.w;
        } else {
            float2 v = *reinterpret_cast<const float2*>(hr);
            acc[0] += alpha * v.x; acc[1] += alpha * v.y;
        }
    }

    float* op = out + (size_t)node * (H * C) + head * C + cb;
#pragma unroll
    for (int j = 0; j < CPL; j++) {
        float v = acc[j] + bias[head * C + cb + j];
        if (RELU) v = fmaxf(v, 0.f);
        op[j] = v;
    }
}

// ---------------- pooling + final linear ------------------------------------
__global__ void pool_zero_kernel(float* pool, float* cnt) {
    int i = blockIdx.x * blockDim.x + threadIdx.x;
    if (i < NGRAPH * 64) pool[i] = 0.f;
    if (i < NGRAPH) cnt[i] = 0.f;
}

__global__ void pool_add_kernel(const float* __restrict__ g, const int* __restrict__ batch,
                                float* __restrict__ pool, float* __restrict__ cnt, int n) {
    int node = blockIdx.x * 4 + (threadIdx.x >> 5);
    int lane = threadIdx.x & 31;
    if (node >= n) return;
    int b = batch[node];
    atomicAdd(&pool[b * 64 + lane], g[(size_t)node * 64 + lane]);
    atomicAdd(&pool[b * 64 + lane + 32], g[(size_t)node * 64 + lane + 32]);
    if (lane == 0) atomicAdd(&cnt[b], 1.f);
}

__global__ void final_kernel(const float* __restrict__ pool, const float* __restrict__ cnt,
                             const float* __restrict__ linW, const float* __restrict__ linb,
                             float* __restrict__ out) {
    int gph = blockIdx.x;
    int o = threadIdx.x;
    float invc = 1.f / fmaxf(cnt[gph], 1.f);
    float acc = linb[o];
#pragma unroll 8
    for (int c = 0; c < 64; c++) acc += pool[gph * 64 + c] * invc * linW[c * 64 + o];
    out[gph * 64 + o] = acc;
}

// ---------------- driver -----------------------------------------------------
extern "C" void kernel_launch(void* const* d_in, const int* in_sizes, int n_in,
                              void* d_out, int out_size) {
    const float* x     = (const float*)d_in[0];
    const int*   ei    = (const int*)d_in[1];     // int32
    const int*   batch = (const int*)d_in[3];     // int32
    const float* W1   = (const float*)d_in[4];
    const float* a1s  = (const float*)d_in[5];
    const float* a1d  = (const float*)d_in[6];
    const float* b1   = (const float*)d_in[7];
    const float* W2   = (const float*)d_in[8];
    const float* a2s  = (const float*)d_in[9];
    const float* a2d  = (const float*)d_in[10];
    const float* b2   = (const float*)d_in[11];
    const float* W3   = (const float*)d_in[12];
    const float* a3s  = (const float*)d_in[13];
    const float* a3d  = (const float*)d_in[14];
    const float* b3   = (const float*)d_in[15];
    const float* linW = (const float*)d_in[16];
    const float* linb = (const float*)d_in[17];
    float* out = (float*)d_out;

    int n  = in_sizes[0] / 128;
    int E  = in_sizes[1] / 2;
    int ET = E + n;

    float *A, *B, *als, *ald, *pool, *cnt;
    int *deg, *off, *cur, *csrc;
    cudaGetSymbolAddress((void**)&A,    g_A);
    cudaGetSymbolAddress((void**)&B,    g_Bb);
    cudaGetSymbolAddress((void**)&als,  g_als);
    cudaGetSymbolAddress((void**)&ald,  g_ald);
    cudaGetSymbolAddress((void**)&deg,  g_deg);
    cudaGetSymbolAddress((void**)&off,  g_off);
    cudaGetSymbolAddress((void**)&cur,  g_cur);
    cudaGetSymbolAddress((void**)&csrc, g_csrc);
    cudaGetSymbolAddress((void**)&pool, g_pool);
    cudaGetSymbolAddress((void**)&cnt,  g_cnt);

    // ---- CSR by dst
    zero_int_kernel<<<(n + 255) / 256, 256>>>(deg, n);
    hist_kernel<<<(ET + 255) / 256, 256>>>(ei, E, ET, deg);
    scan_kernel<<<1, 1024>>>(deg, off, cur, n);
    scatter_kernel<<<(ET + 255) / 256, 256>>>(ei, E, ET, cur, csrc);

    int nwb = (n + 3) / 4;
    int gb = (n + 127) / 128;

    // ---- Layer 1: [N,128] @ [128,256], H=4, C=64, ReLU
    {
        dim3 grid(gb, 4);
        gemm_tf32_kernel<<<grid, 256>>>(x, W1, A, n, 128, 256);
        attn_kernel<4, 64><<<n, 128>>>(A, a1s, a1d, als, ald, n);
        agg_kernel<4, 64, true><<<nwb, 128>>>(A, als, ald, b1, off, csrc, B, n);
    }
    // ---- Layer 2: [N,256] @ [256,256], H=4, C=64, ReLU
    {
        dim3 grid(gb, 4);
        gemm_tf32_kernel<<<grid, 256>>>(B, W2, A, n, 256, 256);
        attn_kernel<4, 64><<<n, 128>>>(A, a2s, a2d, als, ald, n);
        agg_kernel<4, 64, true><<<nwb, 128>>>(A, als, ald, b2, off, csrc, B, n);
    }
    // ---- Layer 3: [N,256] @ [256,64], H=1, C=64, no ReLU
    {
        dim3 grid(gb, 1);
        gemm_tf32_kernel<<<grid, 256>>>(B, W3, A, n, 256, 64);
        attn_kernel<1, 64><<<n, 32>>>(A, a3s, a3d, als, ald, n);
        agg_kernel<1, 64, false><<<nwb, 128>>>(A, als, ald, b3, off, csrc, B, n);
    }

    // ---- global mean pool + linear
    pool_zero_kernel<<<16, 256>>>(pool, cnt);
    pool_add_kernel<<<nwb, 128>>>(B, batch, pool, cnt, n);
    final_kernel<<<NGRAPH, 64>>>(pool, cnt, linW, linb, out);
}

// round 4
// speedup vs baseline: 1.5594x; 1.1760x over previous
#include <cuda_runtime.h>
#include <cstdint>

#define NMAX 50000
#define NGRAPH 64
#define ET_MAX 860000

// ---------------- scratch (device globals; no allocations allowed) ----------
__device__ float g_A[NMAX * 256];
__device__ float g_Bb[NMAX * 256];
__device__ float g_als[NMAX * 4];
__device__ float g_ald[NMAX * 4];
__device__ int   g_deg[NMAX];
__device__ int   g_off[NMAX + 1];
__device__ int   g_cur[NMAX];
__device__ int   g_csrc[ET_MAX];
__device__ float g_pool[NGRAPH * 64];
__device__ float g_cnt[NGRAPH];

// ---------------- CSR build --------------------------------------------------
__global__ void zero_int_kernel(int* p, int n) {
    int i = blockIdx.x * blockDim.x + threadIdx.x;
    if (i < n) p[i] = 0;
}

__global__ void zero2_kernel(float* a, float* b, int n) {
    int i = blockIdx.x * blockDim.x + threadIdx.x;
    if (i < n) { a[i] = 0.f; b[i] = 0.f; }
}

__global__ void hist_kernel(const int* __restrict__ ei, int E, int ET,
                            int* __restrict__ deg) {
    int e = blockIdx.x * blockDim.x + threadIdx.x;
    if (e >= ET) return;
    int d = (e < E) ? ei[E + e] : (e - E);
    atomicAdd(&deg[d], 1);
}

__global__ void scan_kernel(const int* __restrict__ deg, int* __restrict__ off,
                            int* __restrict__ cur, int n) {
    __shared__ int warpsum[32];
    const int T = 1024;
    int chunk = (n + T - 1) / T;
    int start = threadIdx.x * chunk;
    int end = start + chunk; if (end > n) end = n;
    int s = 0;
    for (int i = start; i < end; i++) s += deg[i];
    int lane = threadIdx.x & 31, wid = threadIdx.x >> 5;
    int v = s;
#pragma unroll
    for (int o = 1; o < 32; o <<= 1) {
        int t = __shfl_up_sync(~0u, v, o);
        if (lane >= o) v += t;
    }
    if (lane == 31) warpsum[wid] = v;
    __syncthreads();
    if (wid == 0) {
        int w = warpsum[lane];
#pragma unroll
        for (int o = 1; o < 32; o <<= 1) {
            int t = __shfl_up_sync(~0u, w, o);
            if (lane >= o) w += t;
        }
        warpsum[lane] = w;
    }
    __syncthreads();
    int excl = v - s + (wid > 0 ? warpsum[wid - 1] : 0);
    if (threadIdx.x == 0) off[0] = 0;
    int run = excl;
    for (int i = start; i < end; i++) {
        int d = deg[i];
        cur[i] = run;
        run += d;
        off[i + 1] = run;
    }
}

__global__ void scatter_kernel(const int* __restrict__ ei, int E, int ET,
                               int* __restrict__ cur, int* __restrict__ csrc) {
    int e = blockIdx.x * blockDim.x + threadIdx.x;
    if (e >= ET) return;
    int s, d;
    if (e < E) { s = ei[e]; d = ei[E + e]; }
    else       { s = e - E; d = e - E; }
    int pos = atomicAdd(&cur[d], 1);
    csrc[pos] = s;
}

// ---------------- tf32 GEMM with cp.async pipeline + fused attn epilogue ----
__device__ __forceinline__ uint32_t f2tf32(float v) {
    uint32_t t;
    asm("cvt.rna.tf32.f32 %0, %1;" : "=r"(t) : "f"(v));
    return t;
}

__device__ __forceinline__ void cp16(uint32_t dst, const void* src, int sz) {
    asm volatile("cp.async.ca.shared.global [%0], [%1], 16, %2;\n"
                 :: "r"(dst), "l"(src), "r"(sz));
}

#define ASTRIDE 36   // bank = 4*gid + tig : conflict-free
#define BSTRIDE 72   // bank = 8*tig + gid : conflict-free
#define ABUF (128 * ASTRIDE)
#define BBUF (32 * BSTRIDE)
#define GEMM_SMEM ((2 * ABUF + 2 * BBUF) * 4)

__global__ __launch_bounds__(256, 2)
void gemm_attn_kernel(const float* __restrict__ A, const float* __restrict__ W,
                      float* __restrict__ C,
                      const float* __restrict__ a_src, const float* __restrict__ a_dst,
                      float* __restrict__ als, float* __restrict__ ald,
                      int M, int K, int Nc, int H) {
    extern __shared__ float sm_[];
    float* AsBase = sm_;                  // 2 * ABUF
    float* BsBase = sm_ + 2 * ABUF;       // 2 * BBUF

    const int tid = threadIdx.x;
    const int lane = tid & 31;
    const int wid = tid >> 5;
    const int wr = wid >> 1;
    const int wc = wid & 1;
    const int gid = lane >> 2;
    const int tig = lane & 3;

    const int rowBase = blockIdx.x * 128;
    const int colBase = blockIdx.y * 64;
    const int head = colBase >> 6;        // C == 64 always

    float acc[2][4][4];
#pragma unroll
    for (int mt = 0; mt < 2; mt++)
#pragma unroll
        for (int nt = 0; nt < 4; nt++)
#pragma unroll
            for (int j = 0; j < 4; j++) acc[mt][nt][j] = 0.f;

    const int KT = K >> 5;

    auto load_tiles = [&](int kt, int b) {
        int k0 = kt << 5;
        float* As = AsBase + b * ABUF;
        float* Bs = BsBase + b * BBUF;
#pragma unroll
        for (int i = 0; i < 4; i++) {
            int f4 = tid + (i << 8);
            int r = f4 >> 3, c4 = (f4 & 7) << 2;
            int gr = rowBase + r;
            const float* src = A + (size_t)(gr < M ? gr : 0) * K + k0 + c4;
            uint32_t d = (uint32_t)__cvta_generic_to_shared(As + r * ASTRIDE + c4);
            cp16(d, src, gr < M ? 16 : 0);
        }
#pragma unroll
        for (int i = 0; i < 2; i++) {
            int f4 = tid + (i << 8);
            int r = f4 >> 4, c4 = (f4 & 15) << 2;
            const float* src = W + (size_t)(k0 + r) * Nc + colBase + c4;
            uint32_t d = (uint32_t)__cvta_generic_to_shared(Bs + r * BSTRIDE + c4);
            cp16(d, src, 16);
        }
        asm volatile("cp.async.commit_group;");
    };

    load_tiles(0, 0);

    for (int kt = 0; kt < KT; kt++) {
        int b = kt & 1;
        if (kt + 1 < KT) {
            load_tiles(kt + 1, b ^ 1);
            asm volatile("cp.async.wait_group 1;");
        } else {
            asm volatile("cp.async.wait_group 0;");
        }
        __syncthreads();

        float* As = AsBase + b * ABUF;
        float* Bs = BsBase + b * BBUF;
#pragma unroll
        for (int ks = 0; ks < 4; ks++) {
            const int kk = ks << 3;
            uint32_t af[2][4];
#pragma unroll
            for (int mt = 0; mt < 2; mt++) {
                int r = wr * 32 + mt * 16 + gid;
                af[mt][0] = f2tf32(As[r * ASTRIDE + kk + tig]);
                af[mt][1] = f2tf32(As[(r + 8) * ASTRIDE + kk + tig]);
                af[mt][2] = f2tf32(As[r * ASTRIDE + kk + tig + 4]);
                af[mt][3] = f2tf32(As[(r + 8) * ASTRIDE + kk + tig + 4]);
            }
            uint32_t bf[4][2];
#pragma unroll
            for (int nt = 0; nt < 4; nt++) {
                int c = wc * 32 + nt * 8 + gid;
                bf[nt][0] = f2tf32(Bs[(kk + tig) * BSTRIDE + c]);
                bf[nt][1] = f2tf32(Bs[(kk + tig + 4) * BSTRIDE + c]);
            }
#pragma unroll
            for (int mt = 0; mt < 2; mt++)
#pragma unroll
                for (int nt = 0; nt < 4; nt++) {
                    asm volatile(
                        "mma.sync.aligned.m16n8k8.row.col.f32.tf32.tf32.f32 "
                        "{%0,%1,%2,%3}, {%4,%5,%6,%7}, {%8,%9}, {%0,%1,%2,%3};"
                        : "+f"(acc[mt][nt][0]), "+f"(acc[mt][nt][1]),
                          "+f"(acc[mt][nt][2]), "+f"(acc[mt][nt][3])
                        : "r"(af[mt][0]), "r"(af[mt][1]),
                          "r"(af[mt][2]), "r"(af[mt][3]),
                          "r"(bf[nt][0]), "r"(bf[nt][1]));
                }
        }
        __syncthreads();
    }

    // attn weight vectors for this thread's 8 channels (head fixed per block)
    float asv[8], adv[8];
#pragma unroll
    for (int nt = 0; nt < 4; nt++) {
        int ch = wc * 32 + nt * 8 + tig * 2;
        asv[nt * 2]     = a_src[head * 64 + ch];
        asv[nt * 2 + 1] = a_src[head * 64 + ch + 1];
        adv[nt * 2]     = a_dst[head * 64 + ch];
        adv[nt * 2 + 1] = a_dst[head * 64 + ch + 1];
    }

#pragma unroll
    for (int mt = 0; mt < 2; mt++) {
        int r0 = rowBase + wr * 32 + mt * 16 + gid;
        int r1 = r0 + 8;
        float ps0 = 0.f, pd0 = 0.f, ps1 = 0.f, pd1 = 0.f;
#pragma unroll
        for (int nt = 0; nt < 4; nt++) {
            int c = colBase + wc * 32 + nt * 8 + tig * 2;
            if (r0 < M)
                *reinterpret_cast<float2*>(C + (size_t)r0 * Nc + c) =
                    make_float2(acc[mt][nt][0], acc[mt][nt][1]);
            if (r1 < M)
                *reinterpret_cast<float2*>(C + (size_t)r1 * Nc + c) =
                    make_float2(acc[mt][nt][2], acc[mt][nt][3]);
            ps0 += acc[mt][nt][0] * asv[nt * 2] + acc[mt][nt][1] * asv[nt * 2 + 1];
            pd0 += acc[mt][nt][0] * adv[nt * 2] + acc[mt][nt][1] * adv[nt * 2 + 1];
            ps1 += acc[mt][nt][2] * asv[nt * 2] + acc[mt][nt][3] * asv[nt * 2 + 1];
            pd1 += acc[mt][nt][2] * adv[nt * 2] + acc[mt][nt][3] * adv[nt * 2 + 1];
        }
        ps0 += __shfl_xor_sync(~0u, ps0, 1); ps0 += __shfl_xor_sync(~0u, ps0, 2);
        pd0 += __shfl_xor_sync(~0u, pd0, 1); pd0 += __shfl_xor_sync(~0u, pd0, 2);
        ps1 += __shfl_xor_sync(~0u, ps1, 1); ps1 += __shfl_xor_sync(~0u, ps1, 2);
        pd1 += __shfl_xor_sync(~0u, pd1, 1); pd1 += __shfl_xor_sync(~0u, pd1, 2);
        if (tig == 0) {
            if (r0 < M) { atomicAdd(&als[r0 * H + head], ps0); atomicAdd(&ald[r0 * H + head], pd0); }
            if (r1 < M) { atomicAdd(&als[r1 * H + head], ps1); atomicAdd(&ald[r1 * H + head], pd1); }
        }
    }
}

// ---------------- fused per-node online-softmax + aggregation --------------
template <int H, int C, bool RELU>
__global__ void agg_kernel(const float* __restrict__ h, const float* __restrict__ als,
                           const float* __restrict__ ald, const float* __restrict__ bias,
                           const int* __restrict__ off, const int* __restrict__ csrc,
                           float* __restrict__ out, int n) {
    int node = blockIdx.x * 4 + (threadIdx.x >> 5);
    int lane = threadIdx.x & 31;
    if (node >= n) return;
    int beg = off[node], end = off[node + 1];

    float aldv[H], mx[H], sm[H];
#pragma unroll
    for (int t = 0; t < H; t++) {
        aldv[t] = ald[node * H + t];
        mx[t] = -1e30f;
        sm[t] = 0.f;
    }
    // single online pass: running max + rescaled sum
    for (int i = beg + lane; i < end; i += 32) {
        int s = csrc[i];
#pragma unroll
        for (int t = 0; t < H; t++) {
            float l = als[s * H + t] + aldv[t];
            l = l > 0.f ? l : 0.2f * l;
            if (l > mx[t]) {
                sm[t] = sm[t] * __expf(mx[t] - l) + 1.f;
                mx[t] = l;
            } else {
                sm[t] += __expf(l - mx[t]);
            }
        }
    }
    // warp merge of (max, sum)
#pragma unroll
    for (int t = 0; t < H; t++) {
#pragma unroll
        for (int o = 16; o > 0; o >>= 1) {
            float om = __shfl_xor_sync(~0u, mx[t], o);
            float os = __shfl_xor_sync(~0u, sm[t], o);
            float nm = fmaxf(mx[t], om);
            sm[t] = sm[t] * __expf(mx[t] - nm) + os * __expf(om - nm);
            mx[t] = nm;
        }
    }

    constexpr int LPH = 32 / H;
    constexpr int CPL = (H * C) / 32;
    int head = lane / LPH;
    int cb = (lane % LPH) * CPL;

    float mxh = mx[0], aldh = aldv[0], invh = 1.f / (sm[0] + 1e-16f);
#pragma unroll
    for (int t = 1; t < H; t++)
        if (head == t) { mxh = mx[t]; aldh = aldv[t]; invh = 1.f / (sm[t] + 1e-16f); }

    float acc[CPL];
#pragma unroll
    for (int j = 0; j < CPL; j++) acc[j] = 0.f;

    // accumulate pass with (csrc, als) prefetch one edge ahead
    int sN = 0; float alN = 0.f;
    if (beg < end) { sN = csrc[beg]; alN = als[sN * H + head]; }
    for (int i = beg; i < end; i++) {
        int s = sN; float al = alN;
        if (i + 1 < end) { sN = csrc[i + 1]; alN = als[sN * H + head]; }
        float l = al + aldh;
        l = l > 0.f ? l : 0.2f * l;
        float alpha = __expf(l - mxh) * invh;
        const float* hr = h + (size_t)s * (H * C) + head * C + cb;
        if constexpr (CPL == 8) {
            float4 v0 = *reinterpret_cast<const float4*>(hr);
            float4 v1 = *reinterpret_cast<const float4*>(hr + 4);
            acc[0] += alpha * v0.x; acc[1] += alpha * v0.y;
            acc[2] += alpha * v0.z; acc[3] += alpha * v0.w;
            acc[4] += alpha * v1.x; acc[5] += alpha * v1.y;
            acc[6] += alpha * v1.z; acc[7] += alpha * v1.w;
        } else {
            float2 v = *reinterpret_cast<const float2*>(hr);
            acc[0] += alpha * v.x; acc[1] += alpha * v.y;
        }
    }

    float* op = out + (size_t)node * (H * C) + head * C + cb;
#pragma unroll
    for (int j = 0; j < CPL; j++) {
        float v = acc[j] + bias[head * C + cb + j];
        if (RELU) v = fmaxf(v, 0.f);
        op[j] = v;
    }
}

// ---------------- pooling + final linear ------------------------------------
__global__ void pool_zero_kernel(float* pool, float* cnt) {
    int i = blockIdx.x * blockDim.x + threadIdx.x;
    if (i < NGRAPH * 64) pool[i] = 0.f;
    if (i < NGRAPH) cnt[i] = 0.f;
}

__global__ void pool_add_kernel(const float* __restrict__ g, const int* __restrict__ batch,
                                float* __restrict__ pool, float* __restrict__ cnt, int n) {
    int node = blockIdx.x * 4 + (threadIdx.x >> 5);
    int lane = threadIdx.x & 31;
    if (node >= n) return;
    int b = batch[node];
    atomicAdd(&pool[b * 64 + lane], g[(size_t)node * 64 + lane]);
    atomicAdd(&pool[b * 64 + lane + 32], g[(size_t)node * 64 + lane + 32]);
    if (lane == 0) atomicAdd(&cnt[b], 1.f);
}

__global__ void final_kernel(const float* __restrict__ pool, const float* __restrict__ cnt,
                             const float* __restrict__ linW, const float* __restrict__ linb,
                             float* __restrict__ out) {
    int gph = blockIdx.x;
    int o = threadIdx.x;
    float invc = 1.f / fmaxf(cnt[gph], 1.f);
    float acc = linb[o];
#pragma unroll 8
    for (int c = 0; c < 64; c++) acc += pool[gph * 64 + c] * invc * linW[c * 64 + o];
    out[gph * 64 + o] = acc;
}

// ---------------- driver -----------------------------------------------------
extern "C" void kernel_launch(void* const* d_in, const int* in_sizes, int n_in,
                              void* d_out, int out_size) {
    const float* x     = (const float*)d_in[0];
    const int*   ei    = (const int*)d_in[1];
    const int*   batch = (const int*)d_in[3];
    const float* W1   = (const float*)d_in[4];
    const float* a1s  = (const float*)d_in[5];
    const float* a1d  = (const float*)d_in[6];
    const float* b1   = (const float*)d_in[7];
    const float* W2   = (const float*)d_in[8];
    const float* a2s  = (const float*)d_in[9];
    const float* a2d  = (const float*)d_in[10];
    const float* b2   = (const float*)d_in[11];
    const float* W3   = (const float*)d_in[12];
    const float* a3s  = (const float*)d_in[13];
    const float* a3d  = (const float*)d_in[14];
    const float* b3   = (const float*)d_in[15];
    const float* linW = (const float*)d_in[16];
    const float* linb = (const float*)d_in[17];
    float* out = (float*)d_out;

    int n  = in_sizes[0] / 128;
    int E  = in_sizes[1] / 2;
    int ET = E + n;

    float *A, *B, *als, *ald, *pool, *cnt;
    int *deg, *off, *cur, *csrc;
    cudaGetSymbolAddress((void**)&A,    g_A);
    cudaGetSymbolAddress((void**)&B,    g_Bb);
    cudaGetSymbolAddress((void**)&als,  g_als);
    cudaGetSymbolAddress((void**)&ald,  g_ald);
    cudaGetSymbolAddress((void**)&deg,  g_deg);
    cudaGetSymbolAddress((void**)&off,  g_off);
    cudaGetSymbolAddress((void**)&cur,  g_cur);
    cudaGetSymbolAddress((void**)&csrc, g_csrc);
    cudaGetSymbolAddress((void**)&pool, g_pool);
    cudaGetSymbolAddress((void**)&cnt,  g_cnt);

    cudaFuncSetAttribute(gemm_attn_kernel,
                         cudaFuncAttributeMaxDynamicSharedMemorySize, GEMM_SMEM);

    // ---- CSR by dst
    zero_int_kernel<<<(n + 255) / 256, 256>>>(deg, n);
    hist_kernel<<<(ET + 255) / 256, 256>>>(ei, E, ET, deg);
    scan_kernel<<<1, 1024>>>(deg, off, cur, n);
    scatter_kernel<<<(ET + 255) / 256, 256>>>(ei, E, ET, cur, csrc);

    int nwb = (n + 3) / 4;
    int gb = (n + 127) / 128;
    int zb = (n * 4 + 255) / 256;

    // ---- Layer 1: [N,128] @ [128,256], H=4
    zero2_kernel<<<zb, 256>>>(als, ald, n * 4);
    gemm_attn_kernel<<<dim3(gb, 4), 256, GEMM_SMEM>>>(x, W1, A, a1s, a1d, als, ald, n, 128, 256, 4);
    agg_kernel<4, 64, true><<<nwb, 128>>>(A, als, ald, b1, off, csrc, B, n);

    // ---- Layer 2: [N,256] @ [256,256], H=4
    zero2_kernel<<<zb, 256>>>(als, ald, n * 4);
    gemm_attn_kernel<<<dim3(gb, 4), 256, GEMM_SMEM>>>(B, W2, A, a2s, a2d, als, ald, n, 256, 256, 4);
    agg_kernel<4, 64, true><<<nwb, 128>>>(A, als, ald, b2, off, csrc, B, n);

    // ---- Layer 3: [N,256] @ [256,64], H=1
    zero2_kernel<<<(n + 255) / 256, 256>>>(als, ald, n);
    gemm_attn_kernel<<<dim3(gb, 1), 256, GEMM_SMEM>>>(B, W3, A, a3s, a3d, als, ald, n, 256, 64, 1);
    agg_kernel<1, 64, false><<<nwb, 128>>>(A, als, ald, b3, off, csrc, B, n);

    // ---- global mean pool + linear
    pool_zero_kernel<<<16, 256>>>(pool, cnt);
    pool_add_kernel<<<nwb, 128>>>(B, batch, pool, cnt, n);
    final_kernel<<<NGRAPH, 64>>>(pool, cnt, linW, linb, out);
}